// round 11
// baseline (speedup 1.0000x reference)
#include <cuda_runtime.h>
#include <cuda_bf16.h>
#include <math.h>
#include <stdint.h>

typedef unsigned long long ull;

#define T_STEPS 64
#define BATCH   32
#define VOCAB   32000
#define HDIM    512
#define G4      2048
#define MTOT    (T_STEPS * BATCH)   // 2048
#define KX      1536                // 3 * HDIM (bf16x3 folded K)

// ---------------- scratch (static __device__, allocation-free) ----------------
__device__ float  g_XPt[(size_t)T_STEPS * G4 * BATCH];     // [t][g][b] input proj + biases
__device__ float4 g_hT4[2][128 * 32];                      // [k4][b] hidden, float4 over k
__device__ float  g_cT[HDIM * BATCH];                      // [j][b] cell state (init source)
__device__ float  g_H[(size_t)MTOT * HDIM];                // [i][k] tentative hidden
__device__ float4 g_W4[HDIM * HDIM];                       // [j][k] -> (wi, wf, wg, wo)
__device__ __align__(16) __nv_bfloat16 g_HX[(size_t)MTOT * KX];    // [i][hi|hi|lo]
__device__ __align__(16) __nv_bfloat16 g_WX[(size_t)VOCAB * KX];   // [v][hi|lo|hi]
__device__ __align__(16) __nv_bfloat16 g_EX[(size_t)MTOT * KX];    // emb[tok[i]] split
__device__ __align__(16) __nv_bfloat16 g_WIX[(size_t)G4 * KX];     // W_ih split
__device__ unsigned g_bar_gen;
__device__ unsigned g_bar_cnt;

// ---------------- helpers ----------------
__device__ __forceinline__ ull pack2(float lo, float hi) {
    ull r; asm("mov.b64 %0, {%1, %2};" : "=l"(r) : "f"(lo), "f"(hi)); return r;
}
__device__ __forceinline__ void unpack2(ull v, float& lo, float& hi) {
    unsigned a, b; asm("mov.b64 {%0, %1}, %2;" : "=r"(a), "=r"(b) : "l"(v));
    lo = __uint_as_float(a); hi = __uint_as_float(b);
}
__device__ __forceinline__ void ffma2(ull& acc, ull a, ull b) {
    asm("fma.rn.f32x2 %0, %1, %2, %0;" : "+l"(acc) : "l"(a), "l"(b));
}
__device__ __forceinline__ ull d2u(double d) { return (ull)__double_as_longlong(d); }
__device__ __forceinline__ uint32_t smem_u32(const void* p) {
    uint32_t a;
    asm("{ .reg .u64 t; cvta.to.shared.u64 t, %1; cvt.u32.u64 %0, t; }" : "=r"(a) : "l"(p));
    return a;
}
__device__ __forceinline__ void cp16(uint32_t saddr, const void* gaddr) {
    asm volatile("cp.async.cg.shared.global [%0], [%1], 16;" :: "r"(saddr), "l"(gaddr));
}
__device__ __forceinline__ uint4 ldsm_x4(uint32_t addr) {
    uint4 r;
    asm volatile("ldmatrix.sync.aligned.m8n8.x4.shared.b16 {%0,%1,%2,%3}, [%4];"
                 : "=r"(r.x), "=r"(r.y), "=r"(r.z), "=r"(r.w) : "r"(addr));
    return r;
}
__device__ __forceinline__ void mma16816(float* c, uint4 a, uint32_t b0, uint32_t b1) {
    asm volatile(
        "mma.sync.aligned.m16n8k16.row.col.f32.bf16.bf16.f32 "
        "{%0,%1,%2,%3}, {%4,%5,%6,%7}, {%8,%9}, {%0,%1,%2,%3};"
        : "+f"(c[0]), "+f"(c[1]), "+f"(c[2]), "+f"(c[3])
        : "r"(a.x), "r"(a.y), "r"(a.z), "r"(a.w), "r"(b0), "r"(b1));
}
__device__ __forceinline__ unsigned ld_acq(const unsigned* p) {
    unsigned v; asm volatile("ld.acquire.gpu.u32 %0, [%1];" : "=r"(v) : "l"(p)); return v;
}
__device__ __forceinline__ float4 ldcg4(const float4* p) {
    float4 v;
    asm volatile("ld.global.cg.v4.f32 {%0,%1,%2,%3}, [%4];"
                 : "=f"(v.x), "=f"(v.y), "=f"(v.z), "=f"(v.w) : "l"(p));
    return v;
}

// ================= HMMA GEMM: C[M x N] = A . B^T (+bias) over folded K'=1536 =================
// A/B operands are selected INSIDE the kernel from the template parameter — __device__
// globals must never be passed as kernel arguments from host code (host shadow address!).
// EPI 0: A=g_HX, B=g_WX, out = logits + b_fc.   EPI 1: A=g_EX, B=g_WIX, -> g_XPt + b_ih+b_hh.
#define STAGE_B 32768
#define NSTAGE 24

template <int EPI>
__global__ void __launch_bounds__(256, 2)
mma_gemm(const float* __restrict__ bias0,
         const float* __restrict__ bias1,
         float* __restrict__ out) {
    const __nv_bfloat16* __restrict__ Asrc = (EPI == 0) ? g_HX : g_EX;
    const __nv_bfloat16* __restrict__ Bsrc = (EPI == 0) ? g_WX : g_WIX;

    extern __shared__ char sm[];
    uint32_t smb = smem_u32(sm);
    int tid = threadIdx.x, wid = tid >> 5, lane = tid & 31;
    int i0 = blockIdx.x * 128;
    int v0 = blockIdx.y * 128;
    int m0w = (wid & 1) * 64;
    int n0w = (wid >> 1) * 32;

    int lrow = tid >> 3, lseg = tid & 7;
    int lplane = lseg >> 1, lhalf = lseg & 1;
    const __nv_bfloat16* gA = Asrc + (size_t)(i0 + lrow) * KX + lseg * 8;
    const __nv_bfloat16* gB = Bsrc + (size_t)(v0 + lrow) * KX + lseg * 8;

    auto issue_stage = [&](int s) {
        uint32_t sb = (uint32_t)((s & 1) * STAGE_B);
        size_t gk = (size_t)s * 64;
#pragma unroll
        for (int i = 0; i < 4; i++) {
            uint32_t ro = (uint32_t)(((lrow + i * 32 + lplane) & 127) * 32)
                        + (uint32_t)(lplane * 4096 + lhalf * 16);
            cp16(smb + sb + ro,         gA + gk + (size_t)i * 32 * KX);
            cp16(smb + sb + 16384 + ro, gB + gk + (size_t)i * 32 * KX);
        }
        asm volatile("cp.async.commit_group;");
    };

    float acc[4][4][4];
#pragma unroll
    for (int a = 0; a < 4; a++)
#pragma unroll
        for (int b = 0; b < 4; b++)
#pragma unroll
            for (int r = 0; r < 4; r++) acc[a][b][r] = 0.0f;

    issue_stage(0);
    issue_stage(1);

    for (int s = 0; s < NSTAGE; s++) {
        asm volatile("cp.async.wait_group 1;");
        __syncthreads();
        uint32_t base = smb + (uint32_t)((s & 1) * STAGE_B);
#pragma unroll
        for (int p = 0; p < 4; p++) {
            uint32_t abase = base + p * 4096;
            uint32_t bbase = abase + 16384;
            uint32_t brow0 = (uint32_t)(n0w + (lane & 7) + ((lane >> 4) << 3));
            uint32_t bhalf = (uint32_t)((lane >> 3) & 1);
            uint4 bf01 = ldsm_x4(bbase + (((brow0 + p) & 127) * 32) + bhalf * 16);
            uint4 bf23 = ldsm_x4(bbase + (((brow0 + 16 + p) & 127) * 32) + bhalf * 16);
            uint32_t arow = (uint32_t)(m0w + (lane & 15));
            uint32_t ahalf = (uint32_t)(lane >> 4);
            uint4 af[4];
#pragma unroll
            for (int im = 0; im < 4; im++)
                af[im] = ldsm_x4(abase + (((arow + im * 16 + p) & 127) * 32) + ahalf * 16);
#pragma unroll
            for (int im = 0; im < 4; im++) {
                mma16816(acc[im][0], af[im], bf01.x, bf01.y);
                mma16816(acc[im][1], af[im], bf01.z, bf01.w);
                mma16816(acc[im][2], af[im], bf23.x, bf23.y);
                mma16816(acc[im][3], af[im], bf23.z, bf23.w);
            }
        }
        __syncthreads();
        if (s + 2 < NSTAGE) issue_stage(s + 2);
        else asm volatile("cp.async.commit_group;");
    }

    // ---------------- epilogue ----------------
    int gm = lane >> 2, gn = 2 * (lane & 3);
    if (EPI == 0) {
#pragma unroll
        for (int im = 0; im < 4; im++) {
#pragma unroll
            for (int jn = 0; jn < 4; jn++) {
                int col = v0 + n0w + jn * 8 + gn;
                float2 bb = *(const float2*)(bias0 + col);
                int row = i0 + m0w + im * 16 + gm;
                float2 o0 = make_float2(acc[im][jn][0] + bb.x, acc[im][jn][1] + bb.y);
                float2 o1 = make_float2(acc[im][jn][2] + bb.x, acc[im][jn][3] + bb.y);
                __stcs((float2*)(out + (size_t)row * VOCAB + col), o0);
                __stcs((float2*)(out + (size_t)(row + 8) * VOCAB + col), o1);
            }
        }
    } else {
#pragma unroll
        for (int im = 0; im < 4; im++) {
#pragma unroll
            for (int jn = 0; jn < 4; jn++) {
                int col = v0 + n0w + jn * 8 + gn;
                float b0 = bias0[col] + bias1[col];
                float b1 = bias0[col + 1] + bias1[col + 1];
                int r0 = i0 + m0w + im * 16 + gm;
                int r1 = r0 + 8;
                size_t base0 = (size_t)(r0 >> 5) * (G4 * BATCH) + (r0 & 31);
                size_t base1 = (size_t)(r1 >> 5) * (G4 * BATCH) + (r1 & 31);
                g_XPt[base0 + (size_t)col * 32]       = acc[im][jn][0] + b0;
                g_XPt[base0 + (size_t)(col + 1) * 32] = acc[im][jn][1] + b1;
                g_XPt[base1 + (size_t)col * 32]       = acc[im][jn][2] + b0;
                g_XPt[base1 + (size_t)(col + 1) * 32] = acc[im][jn][3] + b1;
            }
        }
    }
}

// ================= split kernels (fp32 -> bf16 hi/lo, folded-K layout) =================
// A-side layout: [hi | hi | lo].  B-side layout: [hi | lo | hi].
__device__ __forceinline__ void split_row(const float4 w, __nv_bfloat16* row, int k, bool aside) {
    __nv_bfloat16 h0 = __float2bfloat16_rn(w.x), h1 = __float2bfloat16_rn(w.y);
    __nv_bfloat16 h2 = __float2bfloat16_rn(w.z), h3 = __float2bfloat16_rn(w.w);
    __nv_bfloat16 l0 = __float2bfloat16_rn(w.x - __bfloat162float(h0));
    __nv_bfloat16 l1 = __float2bfloat16_rn(w.y - __bfloat162float(h1));
    __nv_bfloat16 l2 = __float2bfloat16_rn(w.z - __bfloat162float(h2));
    __nv_bfloat16 l3 = __float2bfloat16_rn(w.w - __bfloat162float(h3));
    ushort4 hv = make_ushort4(__bfloat16_as_ushort(h0), __bfloat16_as_ushort(h1),
                              __bfloat16_as_ushort(h2), __bfloat16_as_ushort(h3));
    ushort4 lv = make_ushort4(__bfloat16_as_ushort(l0), __bfloat16_as_ushort(l1),
                              __bfloat16_as_ushort(l2), __bfloat16_as_ushort(l3));
    *(ushort4*)(row + k) = hv;
    if (aside) {
        *(ushort4*)(row + 512 + k)  = hv;
        *(ushort4*)(row + 1024 + k) = lv;
    } else {
        *(ushort4*)(row + 512 + k)  = lv;
        *(ushort4*)(row + 1024 + k) = hv;
    }
}

__global__ void split_W(const float* __restrict__ W_fc) {
    int idx = blockIdx.x * 256 + threadIdx.x;        // 32000*128
    int v = idx >> 7, q = idx & 127;
    float4 w = *(const float4*)(W_fc + (size_t)v * HDIM + q * 4);
    split_row(w, g_WX + (size_t)v * KX, q * 4, false);
}
__global__ void split_WI(const float* __restrict__ W_ih) {
    int idx = blockIdx.x * 256 + threadIdx.x;        // 2048*128
    int v = idx >> 7, q = idx & 127;
    float4 w = *(const float4*)(W_ih + (size_t)v * HDIM + q * 4);
    split_row(w, g_WIX + (size_t)v * KX, q * 4, false);
}
__global__ void split_E(const int* __restrict__ tokens, const float* __restrict__ emb) {
    int idx = blockIdx.x * 256 + threadIdx.x;        // 2048*128
    int i = idx >> 7, q = idx & 127;
    int tok = tokens[i];
    float4 w = *(const float4*)(emb + (size_t)tok * HDIM + q * 4);
    split_row(w, g_EX + (size_t)i * KX, q * 4, true);
}
__global__ void split_H(void) {
    int idx = blockIdx.x * 256 + threadIdx.x;        // 2048*128
    int i = idx >> 7, q = idx & 127;
    float4 w = *(const float4*)(g_H + (size_t)i * HDIM + q * 4);
    split_row(w, g_HX + (size_t)i * KX, q * 4, true);
}

// ================= one-time W_hh transpose =================
__global__ void prep_W4(const float* __restrict__ W_hh) {
    int idx = blockIdx.x * 256 + threadIdx.x;
    int j = idx >> 9, k = idx & 511;
    g_W4[(size_t)j * 512 + k] = make_float4(
        W_hh[(size_t)(0 * 512 + j) * 512 + k],
        W_hh[(size_t)(1 * 512 + j) * 512 + k],
        W_hh[(size_t)(2 * 512 + j) * 512 + k],
        W_hh[(size_t)(3 * 512 + j) * 512 + k]);
}

// ================= init (also resets the global barrier each launch/replay) =================
__global__ void init_kernel(const float* __restrict__ h0, const float* __restrict__ c0) {
    int idx = blockIdx.x * blockDim.x + threadIdx.x;
    if (idx == 0) { g_bar_gen = 0; g_bar_cnt = 0; }
    if (idx < BATCH * HDIM) {
        int j = idx >> 5, b = idx & 31;
        ((float*)g_hT4[0])[(j >> 2) * 128 + b * 4 + (j & 3)] = h0[b * HDIM + j];
        g_cT[j * 32 + b] = c0[b * HDIM + j];
    }
}

// ================= fused recurrence: ALL 64 steps in one persistent kernel =================
// 128 CTAs x 256 threads (all co-resident). CTA owns 4 j's; warp w: jl=w>>1, khalf=w&1.
// h staged to smem via L2-only (.cg) loads each step — L1 is NOT coherent across SMs.
// c and own-h carried in registers by the pointwise threads (sole owners).
#define RBLOCKS 128
#define RSMEM   (128 * 32 * 16)   // 64KB: full h buffer staged per step
__global__ void __launch_bounds__(256, 1)
recurrent_fused(const int* __restrict__ tokens) {
    extern __shared__ float4 sh[];        // [128*32] staged h
    __shared__ float4 sred[8][32];
    int tid = threadIdx.x;
    int w = tid >> 5, b = tid & 31;
    int jl = w >> 1, khalf = w & 1;
    int j = blockIdx.x * 4 + jl;

    // double2 == float4 == one k entry (16B); khalf offset = 256 k's
    const double2* dW = (const double2*)(g_W4 + (size_t)j * 512) + (size_t)khalf * 256;
    int j_pw = blockIdx.x * 4 + w;        // pointwise ownership for warps 0..3

    // register-resident state for pointwise threads (sole owners of (j_pw, b))
    float creg = 0.0f, hreg = 0.0f;
    int hslot = 0;
    if (w < 4) {
        hslot = (j_pw >> 2) * 128 + b * 4 + (j_pw & 3);
        creg = g_cT[j_pw * 32 + b];
        hreg = ((const float*)g_hT4[0])[hslot];
    }

    for (int t = 0; t < T_STEPS; t++) {
        // ---- stage h[t&1] into smem through L2 (coherent across SMs) ----
        const float4* hsrc = g_hT4[t & 1];
#pragma unroll
        for (int q = 0; q < 16; q++)
            sh[tid + q * 256] = ldcg4(&hsrc[tid + q * 256]);
        __syncthreads();

        const float4* hp = sh + khalf * 64 * 32;   // 64 k4-groups = 256 k's

        ull aif0 = pack2(0.0f, 0.0f), aif1 = pack2(0.0f, 0.0f);
        ull ago0 = pack2(0.0f, 0.0f), ago1 = pack2(0.0f, 0.0f);

#pragma unroll 4
        for (int kk = 0; kk < 64; kk++) {
            float4  h4 = hp[kk * 32 + b];
            double2 w0 = __ldg(&dW[kk * 4 + 0]);   // k_0: .x=(wi,wf) .y=(wg,wo)
            double2 w1 = __ldg(&dW[kk * 4 + 1]);
            double2 w2 = __ldg(&dW[kk * 4 + 2]);
            double2 w3 = __ldg(&dW[kk * 4 + 3]);
            ull hx = pack2(h4.x, h4.x), hy = pack2(h4.y, h4.y);
            ull hz = pack2(h4.z, h4.z), hw = pack2(h4.w, h4.w);
            ffma2(aif0, hx, d2u(w0.x));
            ffma2(ago0, hx, d2u(w0.y));
            ffma2(aif1, hy, d2u(w1.x));
            ffma2(ago1, hy, d2u(w1.y));
            ffma2(aif0, hz, d2u(w2.x));
            ffma2(ago0, hz, d2u(w2.y));
            ffma2(aif1, hw, d2u(w3.x));
            ffma2(ago1, hw, d2u(w3.y));
        }

        float ia, fa, ib, fb, ga, oa, gb, ob;
        unpack2(aif0, ia, fa); unpack2(aif1, ib, fb);
        unpack2(ago0, ga, oa); unpack2(ago1, gb, ob);
        sred[w][b] = make_float4(ia + ib, fa + fb, ga + gb, oa + ob);
        __syncthreads();

        if (w < 4) {
            float4 s0 = sred[2 * w][b], s1 = sred[2 * w + 1][b];
            size_t xb = (size_t)t * (G4 * BATCH) + (size_t)b;
            float ig = s0.x + s1.x + g_XPt[xb + (size_t)(0 * 512 + j_pw) * 32];
            float fg = s0.y + s1.y + g_XPt[xb + (size_t)(1 * 512 + j_pw) * 32];
            float gg = s0.z + s1.z + g_XPt[xb + (size_t)(2 * 512 + j_pw) * 32];
            float og = s0.w + s1.w + g_XPt[xb + (size_t)(3 * 512 + j_pw) * 32];

            float iv = 1.0f / (1.0f + expf(-ig));
            float fv = 1.0f / (1.0f + expf(-fg));
            float gv = tanhf(gg);
            float ov = 1.0f / (1.0f + expf(-og));

            float ctmp = fv * creg + iv * gv;
            float htmp = ov * tanhf(ctmp);
            bool  msk  = tokens[t * BATCH + b] != 0;   // PAD = 0

            g_H[((size_t)t * BATCH + b) * HDIM + j_pw] = htmp;
            hreg = msk ? htmp : hreg;
            creg = msk ? ctmp : creg;
            ((float*)g_hT4[(t + 1) & 1])[hslot] = hreg;
        }
        __syncthreads();

        // ---- grid-wide barrier (all 128 CTAs co-resident) ----
        if (tid == 0) {
            __threadfence();
            unsigned arrived = atomicAdd(&g_bar_cnt, 1u);
            unsigned target = (unsigned)(t + 1);
            if (arrived == RBLOCKS - 1) {
                atomicExch(&g_bar_cnt, 0u);
                __threadfence();
                atomicExch(&g_bar_gen, target);
            } else {
                while (ld_acq(&g_bar_gen) < target) __nanosleep(32);
            }
            __threadfence();
        }
        __syncthreads();
    }
}

// ================= launch =================
extern "C" void kernel_launch(void* const* d_in, const int* in_sizes, int n_in,
                              void* d_out, int out_size) {
    const int*   tokens = (const int*)d_in[0];
    const float* emb    = (const float*)d_in[1];
    const float* W_ih   = (const float*)d_in[2];
    const float* W_hh   = (const float*)d_in[3];
    const float* b_ih   = (const float*)d_in[4];
    const float* b_hh   = (const float*)d_in[5];
    const float* W_fc   = (const float*)d_in[6];
    const float* b_fc   = (const float*)d_in[7];
    const float* h0     = (const float*)d_in[8];
    const float* c0     = (const float*)d_in[9];
    float* out = (float*)d_out;

    cudaFuncSetAttribute(mma_gemm<0>, cudaFuncAttributeMaxDynamicSharedMemorySize, 2 * STAGE_B);
    cudaFuncSetAttribute(mma_gemm<1>, cudaFuncAttributeMaxDynamicSharedMemorySize, 2 * STAGE_B);
    cudaFuncSetAttribute(recurrent_fused, cudaFuncAttributeMaxDynamicSharedMemorySize, RSMEM);

    init_kernel<<<64, 256>>>(h0, c0);
    prep_W4<<<1024, 256>>>(W_hh);
    split_W<<<16000, 256>>>(W_fc);
    split_WI<<<1024, 256>>>(W_ih);
    split_E<<<1024, 256>>>(tokens, emb);

    // XPt = emb[tok] @ W_ih^T + (b_ih + b_hh):  M=2048, N=2048, K'=1536 (HMMA bf16x3)
    mma_gemm<1><<<dim3(16, 16), 256, 2 * STAGE_B>>>(b_ih, b_hh, nullptr);

    // all 64 LSTM steps in one persistent kernel
    recurrent_fused<<<RBLOCKS, 256, RSMEM>>>(tokens);

    split_H<<<1024, 256>>>();

    // out = HX @ WX^T + b_fc:  M=2048, N=32000, K'=1536 (HMMA bf16x3)
    mma_gemm<0><<<dim3(16, 250), 256, 2 * STAGE_B>>>(b_fc, nullptr, out);
}

// round 12
// speedup vs baseline: 1.0325x; 1.0325x over previous
#include <cuda_runtime.h>
#include <cuda_bf16.h>
#include <math.h>
#include <stdint.h>

typedef unsigned long long ull;

#define T_STEPS 64
#define BATCH   32
#define VOCAB   32000
#define HDIM    512
#define G4      2048
#define MTOT    (T_STEPS * BATCH)   // 2048
#define KX      1536                // 3 * HDIM (bf16x3 folded K)

// ---------------- scratch (static __device__, allocation-free) ----------------
__device__ float  g_XPt[(size_t)T_STEPS * G4 * BATCH];     // [t][g][b] input proj + biases
__device__ float4 g_hT4[2][128 * 32];                      // [k4][b] hidden, float4 over k
__device__ float  g_cT[HDIM * BATCH];                      // [j][b] cell state
__device__ float  g_H[(size_t)MTOT * HDIM];                // [i][k] tentative hidden
__device__ float4 g_W4[HDIM * HDIM];                       // [j][k] -> (wi, wf, wg, wo)
__device__ __align__(16) __nv_bfloat16 g_HX[(size_t)MTOT * KX];    // [i][hi|hi|lo]
__device__ __align__(16) __nv_bfloat16 g_WX[(size_t)VOCAB * KX];   // [v][hi|lo|hi]
__device__ __align__(16) __nv_bfloat16 g_EX[(size_t)MTOT * KX];    // emb[tok[i]] split
__device__ __align__(16) __nv_bfloat16 g_WIX[(size_t)G4 * KX];     // W_ih split

// ---------------- helpers ----------------
__device__ __forceinline__ ull pack2(float lo, float hi) {
    ull r; asm("mov.b64 %0, {%1, %2};" : "=l"(r) : "f"(lo), "f"(hi)); return r;
}
__device__ __forceinline__ void unpack2(ull v, float& lo, float& hi) {
    unsigned a, b; asm("mov.b64 {%0, %1}, %2;" : "=r"(a), "=r"(b) : "l"(v));
    lo = __uint_as_float(a); hi = __uint_as_float(b);
}
__device__ __forceinline__ void ffma2(ull& acc, ull a, ull b) {
    asm("fma.rn.f32x2 %0, %1, %2, %0;" : "+l"(acc) : "l"(a), "l"(b));
}
__device__ __forceinline__ ull d2u(double d) { return (ull)__double_as_longlong(d); }
__device__ __forceinline__ uint32_t smem_u32(const void* p) {
    uint32_t a;
    asm("{ .reg .u64 t; cvta.to.shared.u64 t, %1; cvt.u32.u64 %0, t; }" : "=r"(a) : "l"(p));
    return a;
}
__device__ __forceinline__ void cp16(uint32_t saddr, const void* gaddr) {
    asm volatile("cp.async.cg.shared.global [%0], [%1], 16;" :: "r"(saddr), "l"(gaddr));
}
__device__ __forceinline__ uint4 ldsm_x4(uint32_t addr) {
    uint4 r;
    asm volatile("ldmatrix.sync.aligned.m8n8.x4.shared.b16 {%0,%1,%2,%3}, [%4];"
                 : "=r"(r.x), "=r"(r.y), "=r"(r.z), "=r"(r.w) : "r"(addr));
    return r;
}
__device__ __forceinline__ void mma16816(float* c, uint4 a, uint32_t b0, uint32_t b1) {
    asm volatile(
        "mma.sync.aligned.m16n8k16.row.col.f32.bf16.bf16.f32 "
        "{%0,%1,%2,%3}, {%4,%5,%6,%7}, {%8,%9}, {%0,%1,%2,%3};"
        : "+f"(c[0]), "+f"(c[1]), "+f"(c[2]), "+f"(c[3])
        : "r"(a.x), "r"(a.y), "r"(a.z), "r"(a.w), "r"(b0), "r"(b1));
}
__device__ __forceinline__ float4 ldcg4(const float4* p) {
    float4 v;
    asm volatile("ld.global.cg.v4.f32 {%0,%1,%2,%3}, [%4];"
                 : "=f"(v.x), "=f"(v.y), "=f"(v.z), "=f"(v.w) : "l"(p));
    return v;
}

// ================= HMMA GEMM: C[M x N] = A . B^T (+bias) over folded K'=1536 =================
// A/B operands selected INSIDE the kernel (never pass __device__ globals from host!).
// EPI 0: A=g_HX, B=g_WX, out = logits + b_fc.   EPI 1: A=g_EX, B=g_WIX, -> g_XPt + b_ih+b_hh.
#define STAGE_B 32768
#define NSTAGE 24

template <int EPI>
__global__ void __launch_bounds__(256, 2)
mma_gemm(const float* __restrict__ bias0,
         const float* __restrict__ bias1,
         float* __restrict__ out) {
    const __nv_bfloat16* __restrict__ Asrc = (EPI == 0) ? g_HX : g_EX;
    const __nv_bfloat16* __restrict__ Bsrc = (EPI == 0) ? g_WX : g_WIX;

    extern __shared__ char sm[];
    uint32_t smb = smem_u32(sm);
    int tid = threadIdx.x, wid = tid >> 5, lane = tid & 31;
    int i0 = blockIdx.x * 128;
    int v0 = blockIdx.y * 128;
    int m0w = (wid & 1) * 64;
    int n0w = (wid >> 1) * 32;

    int lrow = tid >> 3, lseg = tid & 7;
    int lplane = lseg >> 1, lhalf = lseg & 1;
    const __nv_bfloat16* gA = Asrc + (size_t)(i0 + lrow) * KX + lseg * 8;
    const __nv_bfloat16* gB = Bsrc + (size_t)(v0 + lrow) * KX + lseg * 8;

    auto issue_stage = [&](int s) {
        uint32_t sb = (uint32_t)((s & 1) * STAGE_B);
        size_t gk = (size_t)s * 64;
#pragma unroll
        for (int i = 0; i < 4; i++) {
            uint32_t ro = (uint32_t)(((lrow + i * 32 + lplane) & 127) * 32)
                        + (uint32_t)(lplane * 4096 + lhalf * 16);
            cp16(smb + sb + ro,         gA + gk + (size_t)i * 32 * KX);
            cp16(smb + sb + 16384 + ro, gB + gk + (size_t)i * 32 * KX);
        }
        asm volatile("cp.async.commit_group;");
    };

    float acc[4][4][4];
#pragma unroll
    for (int a = 0; a < 4; a++)
#pragma unroll
        for (int b = 0; b < 4; b++)
#pragma unroll
            for (int r = 0; r < 4; r++) acc[a][b][r] = 0.0f;

    issue_stage(0);
    issue_stage(1);

    for (int s = 0; s < NSTAGE; s++) {
        asm volatile("cp.async.wait_group 1;");
        __syncthreads();
        uint32_t base = smb + (uint32_t)((s & 1) * STAGE_B);
#pragma unroll
        for (int p = 0; p < 4; p++) {
            uint32_t abase = base + p * 4096;
            uint32_t bbase = abase + 16384;
            uint32_t brow0 = (uint32_t)(n0w + (lane & 7) + ((lane >> 4) << 3));
            uint32_t bhalf = (uint32_t)((lane >> 3) & 1);
            uint4 bf01 = ldsm_x4(bbase + (((brow0 + p) & 127) * 32) + bhalf * 16);
            uint4 bf23 = ldsm_x4(bbase + (((brow0 + 16 + p) & 127) * 32) + bhalf * 16);
            uint32_t arow = (uint32_t)(m0w + (lane & 15));
            uint32_t ahalf = (uint32_t)(lane >> 4);
            uint4 af[4];
#pragma unroll
            for (int im = 0; im < 4; im++)
                af[im] = ldsm_x4(abase + (((arow + im * 16 + p) & 127) * 32) + ahalf * 16);
#pragma unroll
            for (int im = 0; im < 4; im++) {
                mma16816(acc[im][0], af[im], bf01.x, bf01.y);
                mma16816(acc[im][1], af[im], bf01.z, bf01.w);
                mma16816(acc[im][2], af[im], bf23.x, bf23.y);
                mma16816(acc[im][3], af[im], bf23.z, bf23.w);
            }
        }
        __syncthreads();
        if (s + 2 < NSTAGE) issue_stage(s + 2);
        else asm volatile("cp.async.commit_group;");
    }

    // ---------------- epilogue ----------------
    int gm = lane >> 2, gn = 2 * (lane & 3);
    if (EPI == 0) {
#pragma unroll
        for (int im = 0; im < 4; im++) {
#pragma unroll
            for (int jn = 0; jn < 4; jn++) {
                int col = v0 + n0w + jn * 8 + gn;
                float2 bb = *(const float2*)(bias0 + col);
                int row = i0 + m0w + im * 16 + gm;
                float2 o0 = make_float2(acc[im][jn][0] + bb.x, acc[im][jn][1] + bb.y);
                float2 o1 = make_float2(acc[im][jn][2] + bb.x, acc[im][jn][3] + bb.y);
                __stcs((float2*)(out + (size_t)row * VOCAB + col), o0);
                __stcs((float2*)(out + (size_t)(row + 8) * VOCAB + col), o1);
            }
        }
    } else {
#pragma unroll
        for (int im = 0; im < 4; im++) {
#pragma unroll
            for (int jn = 0; jn < 4; jn++) {
                int col = v0 + n0w + jn * 8 + gn;
                float b0 = bias0[col] + bias1[col];
                float b1 = bias0[col + 1] + bias1[col + 1];
                int r0 = i0 + m0w + im * 16 + gm;
                int r1 = r0 + 8;
                size_t base0 = (size_t)(r0 >> 5) * (G4 * BATCH) + (r0 & 31);
                size_t base1 = (size_t)(r1 >> 5) * (G4 * BATCH) + (r1 & 31);
                g_XPt[base0 + (size_t)col * 32]       = acc[im][jn][0] + b0;
                g_XPt[base0 + (size_t)(col + 1) * 32] = acc[im][jn][1] + b1;
                g_XPt[base1 + (size_t)col * 32]       = acc[im][jn][2] + b0;
                g_XPt[base1 + (size_t)(col + 1) * 32] = acc[im][jn][3] + b1;
            }
        }
    }
}

// ================= split kernels (fp32 -> bf16 hi/lo, folded-K layout) =================
// A-side layout: [hi | hi | lo].  B-side layout: [hi | lo | hi].
__device__ __forceinline__ void split_row(const float4 w, __nv_bfloat16* row, int k, bool aside) {
    __nv_bfloat16 h0 = __float2bfloat16_rn(w.x), h1 = __float2bfloat16_rn(w.y);
    __nv_bfloat16 h2 = __float2bfloat16_rn(w.z), h3 = __float2bfloat16_rn(w.w);
    __nv_bfloat16 l0 = __float2bfloat16_rn(w.x - __bfloat162float(h0));
    __nv_bfloat16 l1 = __float2bfloat16_rn(w.y - __bfloat162float(h1));
    __nv_bfloat16 l2 = __float2bfloat16_rn(w.z - __bfloat162float(h2));
    __nv_bfloat16 l3 = __float2bfloat16_rn(w.w - __bfloat162float(h3));
    ushort4 hv = make_ushort4(__bfloat16_as_ushort(h0), __bfloat16_as_ushort(h1),
                              __bfloat16_as_ushort(h2), __bfloat16_as_ushort(h3));
    ushort4 lv = make_ushort4(__bfloat16_as_ushort(l0), __bfloat16_as_ushort(l1),
                              __bfloat16_as_ushort(l2), __bfloat16_as_ushort(l3));
    *(ushort4*)(row + k) = hv;
    if (aside) {
        *(ushort4*)(row + 512 + k)  = hv;
        *(ushort4*)(row + 1024 + k) = lv;
    } else {
        *(ushort4*)(row + 512 + k)  = lv;
        *(ushort4*)(row + 1024 + k) = hv;
    }
}

__global__ void split_W(const float* __restrict__ W_fc) {
    int idx = blockIdx.x * 256 + threadIdx.x;        // 32000*128
    int v = idx >> 7, q = idx & 127;
    float4 w = *(const float4*)(W_fc + (size_t)v * HDIM + q * 4);
    split_row(w, g_WX + (size_t)v * KX, q * 4, false);
}
__global__ void split_WI(const float* __restrict__ W_ih) {
    int idx = blockIdx.x * 256 + threadIdx.x;        // 2048*128
    int v = idx >> 7, q = idx & 127;
    float4 w = *(const float4*)(W_ih + (size_t)v * HDIM + q * 4);
    split_row(w, g_WIX + (size_t)v * KX, q * 4, false);
}
__global__ void split_E(const int* __restrict__ tokens, const float* __restrict__ emb) {
    int idx = blockIdx.x * 256 + threadIdx.x;        // 2048*128
    int i = idx >> 7, q = idx & 127;
    int tok = tokens[i];
    float4 w = *(const float4*)(emb + (size_t)tok * HDIM + q * 4);
    split_row(w, g_EX + (size_t)i * KX, q * 4, true);
}
__global__ void split_H(void) {
    int idx = blockIdx.x * 256 + threadIdx.x;        // 2048*128
    int i = idx >> 7, q = idx & 127;
    float4 w = *(const float4*)(g_H + (size_t)i * HDIM + q * 4);
    split_row(w, g_HX + (size_t)i * KX, q * 4, true);
}

// ================= one-time W_hh transpose =================
__global__ void prep_W4(const float* __restrict__ W_hh) {
    int idx = blockIdx.x * 256 + threadIdx.x;
    int j = idx >> 9, k = idx & 511;
    g_W4[(size_t)j * 512 + k] = make_float4(
        W_hh[(size_t)(0 * 512 + j) * 512 + k],
        W_hh[(size_t)(1 * 512 + j) * 512 + k],
        W_hh[(size_t)(2 * 512 + j) * 512 + k],
        W_hh[(size_t)(3 * 512 + j) * 512 + k]);
}

// ================= init =================
__global__ void init_kernel(const float* __restrict__ h0, const float* __restrict__ c0) {
    int idx = blockIdx.x * blockDim.x + threadIdx.x;
    if (idx < BATCH * HDIM) {
        int j = idx >> 5, b = idx & 31;
        ((float*)g_hT4[0])[(j >> 2) * 128 + b * 4 + (j & 3)] = h0[b * HDIM + j];
        g_cT[j * 32 + b] = c0[b * HDIM + j];
    }
}

// ================= recurrent step: one launch per t (R11-proven body, barrier-free) =================
// 128 CTAs x 256 threads. CTA owns 4 j's; warp w: jl=w>>1, khalf=w&1 (256 k's each).
// Full h staged to smem (8 MB/step chip-wide vs 32 MB with one-j CTAs).
// Kernel-launch boundaries provide the step ordering; c/h carried in global scratch.
#define RBLOCKS 128
#define RSMEM   (128 * 32 * 16)   // 64KB: full h buffer staged per step
__global__ void __launch_bounds__(256, 1)
recurrent_step(const int* __restrict__ tokens, int t) {
    extern __shared__ float4 sh[];        // [128*32] staged h
    __shared__ float4 sred[8][32];
    int tid = threadIdx.x;
    int w = tid >> 5, b = tid & 31;
    int jl = w >> 1, khalf = w & 1;
    int j = blockIdx.x * 4 + jl;

    // double2 == float4 == one k entry (16B); khalf offset = 256 k's
    const double2* dW = (const double2*)(g_W4 + (size_t)j * 512) + (size_t)khalf * 256;
    int j_pw = blockIdx.x * 4 + w;        // pointwise ownership for warps 0..3

    // ---- stage h[t&1] into smem ----
    const float4* hsrc = g_hT4[t & 1];
#pragma unroll
    for (int q = 0; q < 16; q++)
        sh[tid + q * 256] = ldcg4(&hsrc[tid + q * 256]);
    __syncthreads();

    const float4* hp = sh + khalf * 64 * 32;   // 64 k4-groups = 256 k's

    ull aif0 = pack2(0.0f, 0.0f), aif1 = pack2(0.0f, 0.0f);
    ull ago0 = pack2(0.0f, 0.0f), ago1 = pack2(0.0f, 0.0f);

#pragma unroll 4
    for (int kk = 0; kk < 64; kk++) {
        float4  h4 = hp[kk * 32 + b];
        double2 w0 = __ldg(&dW[kk * 4 + 0]);   // k_0: .x=(wi,wf) .y=(wg,wo)
        double2 w1 = __ldg(&dW[kk * 4 + 1]);
        double2 w2 = __ldg(&dW[kk * 4 + 2]);
        double2 w3 = __ldg(&dW[kk * 4 + 3]);
        ull hx = pack2(h4.x, h4.x), hy = pack2(h4.y, h4.y);
        ull hz = pack2(h4.z, h4.z), hw = pack2(h4.w, h4.w);
        ffma2(aif0, hx, d2u(w0.x));
        ffma2(ago0, hx, d2u(w0.y));
        ffma2(aif1, hy, d2u(w1.x));
        ffma2(ago1, hy, d2u(w1.y));
        ffma2(aif0, hz, d2u(w2.x));
        ffma2(ago0, hz, d2u(w2.y));
        ffma2(aif1, hw, d2u(w3.x));
        ffma2(ago1, hw, d2u(w3.y));
    }

    float ia, fa, ib, fb, ga, oa, gb, ob;
    unpack2(aif0, ia, fa); unpack2(aif1, ib, fb);
    unpack2(ago0, ga, oa); unpack2(ago1, gb, ob);
    sred[w][b] = make_float4(ia + ib, fa + fb, ga + gb, oa + ob);
    __syncthreads();

    if (w < 4) {
        float4 s0 = sred[2 * w][b], s1 = sred[2 * w + 1][b];
        size_t xb = (size_t)t * (G4 * BATCH) + (size_t)b;
        float ig = s0.x + s1.x + g_XPt[xb + (size_t)(0 * 512 + j_pw) * 32];
        float fg = s0.y + s1.y + g_XPt[xb + (size_t)(1 * 512 + j_pw) * 32];
        float gg = s0.z + s1.z + g_XPt[xb + (size_t)(2 * 512 + j_pw) * 32];
        float og = s0.w + s1.w + g_XPt[xb + (size_t)(3 * 512 + j_pw) * 32];

        float iv = 1.0f / (1.0f + expf(-ig));
        float fv = 1.0f / (1.0f + expf(-fg));
        float gv = tanhf(gg);
        float ov = 1.0f / (1.0f + expf(-og));

        int hslot = (j_pw >> 2) * 128 + b * 4 + (j_pw & 3);
        float cold = g_cT[j_pw * 32 + b];
        float ctmp = fv * cold + iv * gv;
        float htmp = ov * tanhf(ctmp);
        bool  msk  = tokens[t * BATCH + b] != 0;   // PAD = 0

        g_H[((size_t)t * BATCH + b) * HDIM + j_pw] = htmp;
        float hold = ((const float*)g_hT4[t & 1])[hslot];
        ((float*)g_hT4[(t + 1) & 1])[hslot] = msk ? htmp : hold;
        g_cT[j_pw * 32 + b] = msk ? ctmp : cold;
    }
}

// ================= launch =================
extern "C" void kernel_launch(void* const* d_in, const int* in_sizes, int n_in,
                              void* d_out, int out_size) {
    const int*   tokens = (const int*)d_in[0];
    const float* emb    = (const float*)d_in[1];
    const float* W_ih   = (const float*)d_in[2];
    const float* W_hh   = (const float*)d_in[3];
    const float* b_ih   = (const float*)d_in[4];
    const float* b_hh   = (const float*)d_in[5];
    const float* W_fc   = (const float*)d_in[6];
    const float* b_fc   = (const float*)d_in[7];
    const float* h0     = (const float*)d_in[8];
    const float* c0     = (const float*)d_in[9];
    float* out = (float*)d_out;

    cudaFuncSetAttribute(mma_gemm<0>, cudaFuncAttributeMaxDynamicSharedMemorySize, 2 * STAGE_B);
    cudaFuncSetAttribute(mma_gemm<1>, cudaFuncAttributeMaxDynamicSharedMemorySize, 2 * STAGE_B);
    cudaFuncSetAttribute(recurrent_step, cudaFuncAttributeMaxDynamicSharedMemorySize, RSMEM);

    init_kernel<<<64, 256>>>(h0, c0);
    prep_W4<<<1024, 256>>>(W_hh);
    split_W<<<16000, 256>>>(W_fc);
    split_WI<<<1024, 256>>>(W_ih);
    split_E<<<1024, 256>>>(tokens, emb);

    // XPt = emb[tok] @ W_ih^T + (b_ih + b_hh):  M=2048, N=2048, K'=1536 (HMMA bf16x3)
    mma_gemm<1><<<dim3(16, 16), 256, 2 * STAGE_B>>>(b_ih, b_hh, nullptr);

    // 64 LSTM steps, one launch each (barrier-free; launch = grid sync)
    for (int t = 0; t < T_STEPS; t++)
        recurrent_step<<<RBLOCKS, 256, RSMEM>>>(tokens, t);

    split_H<<<1024, 256>>>();

    // out = HX @ WX^T + b_fc:  M=2048, N=32000, K'=1536 (HMMA bf16x3)
    mma_gemm<0><<<dim3(16, 250), 256, 2 * STAGE_B>>>(b_fc, nullptr, out);
}

// round 13
// speedup vs baseline: 1.1000x; 1.0653x over previous
#include <cuda_runtime.h>
#include <cuda_bf16.h>
#include <math.h>
#include <stdint.h>

typedef unsigned long long ull;

#define T_STEPS 64
#define BATCH   32
#define VOCAB   32000
#define HDIM    512
#define G4      2048
#define MTOT    (T_STEPS * BATCH)   // 2048
#define KX      1536                // 3 * HDIM (bf16x3 folded K)

// ---------------- scratch (static __device__, allocation-free) ----------------
__device__ float  g_XPt[(size_t)T_STEPS * G4 * BATCH];     // [t][g][b] input proj + biases
__device__ float4 g_hT4[2][128 * 32];                      // [k4][b] hidden, float4 over k
__device__ float  g_cT[HDIM * BATCH];                      // [j][b] cell state
__device__ float  g_H[(size_t)MTOT * HDIM];                // [i][k] tentative hidden
__device__ float4 g_W4[HDIM * HDIM];                       // [j][k] -> (wi, wf, wg, wo)
__device__ __align__(16) __nv_bfloat16 g_HX[(size_t)MTOT * KX];    // [i][hi|hi|lo]
__device__ __align__(16) __nv_bfloat16 g_WX[(size_t)VOCAB * KX];   // [v][hi|lo|hi]
__device__ __align__(16) __nv_bfloat16 g_EX[(size_t)MTOT * KX];    // emb[tok[i]] split
__device__ __align__(16) __nv_bfloat16 g_WIX[(size_t)G4 * KX];     // W_ih split

// ---------------- helpers ----------------
__device__ __forceinline__ ull pack2(float lo, float hi) {
    ull r; asm("mov.b64 %0, {%1, %2};" : "=l"(r) : "f"(lo), "f"(hi)); return r;
}
__device__ __forceinline__ void unpack2(ull v, float& lo, float& hi) {
    unsigned a, b; asm("mov.b64 {%0, %1}, %2;" : "=r"(a), "=r"(b) : "l"(v));
    lo = __uint_as_float(a); hi = __uint_as_float(b);
}
__device__ __forceinline__ void ffma2(ull& acc, ull a, ull b) {
    asm("fma.rn.f32x2 %0, %1, %2, %0;" : "+l"(acc) : "l"(a), "l"(b));
}
__device__ __forceinline__ ull d2u(double d) { return (ull)__double_as_longlong(d); }
__device__ __forceinline__ uint32_t smem_u32(const void* p) {
    uint32_t a;
    asm("{ .reg .u64 t; cvta.to.shared.u64 t, %1; cvt.u32.u64 %0, t; }" : "=r"(a) : "l"(p));
    return a;
}
__device__ __forceinline__ void cp16(uint32_t saddr, const void* gaddr) {
    asm volatile("cp.async.cg.shared.global [%0], [%1], 16;" :: "r"(saddr), "l"(gaddr));
}
__device__ __forceinline__ uint4 ldsm_x4(uint32_t addr) {
    uint4 r;
    asm volatile("ldmatrix.sync.aligned.m8n8.x4.shared.b16 {%0,%1,%2,%3}, [%4];"
                 : "=r"(r.x), "=r"(r.y), "=r"(r.z), "=r"(r.w) : "r"(addr));
    return r;
}
__device__ __forceinline__ void mma16816(float* c, uint4 a, uint32_t b0, uint32_t b1) {
    asm volatile(
        "mma.sync.aligned.m16n8k16.row.col.f32.bf16.bf16.f32 "
        "{%0,%1,%2,%3}, {%4,%5,%6,%7}, {%8,%9}, {%0,%1,%2,%3};"
        : "+f"(c[0]), "+f"(c[1]), "+f"(c[2]), "+f"(c[3])
        : "r"(a.x), "r"(a.y), "r"(a.z), "r"(a.w), "r"(b0), "r"(b1));
}

// ================= HMMA GEMM: C[M x N] = A . B^T (+bias), folded K'=1536, 3-stage pipeline =================
// A/B operands selected INSIDE the kernel (never pass __device__ globals from host!).
// EPI 0: A=g_HX, B=g_WX, out = logits + b_fc.   EPI 1: A=g_EX, B=g_WIX, -> g_XPt + b_ih+b_hh.
#define STAGE_B 32768
#define NPIPE   3
#define GEMM_SMEM (NPIPE * STAGE_B)
#define NSTAGE 24

template <int EPI>
__global__ void __launch_bounds__(256, 2)
mma_gemm(const float* __restrict__ bias0,
         const float* __restrict__ bias1,
         float* __restrict__ out) {
    const __nv_bfloat16* __restrict__ Asrc = (EPI == 0) ? g_HX : g_EX;
    const __nv_bfloat16* __restrict__ Bsrc = (EPI == 0) ? g_WX : g_WIX;

    extern __shared__ char sm[];
    uint32_t smb = smem_u32(sm);
    int tid = threadIdx.x, wid = tid >> 5, lane = tid & 31;
    int i0 = blockIdx.x * 128;
    int v0 = blockIdx.y * 128;
    int m0w = (wid & 1) * 64;
    int n0w = (wid >> 1) * 32;

    int lrow = tid >> 3, lseg = tid & 7;
    int lplane = lseg >> 1, lhalf = lseg & 1;
    const __nv_bfloat16* gA = Asrc + (size_t)(i0 + lrow) * KX + lseg * 8;
    const __nv_bfloat16* gB = Bsrc + (size_t)(v0 + lrow) * KX + lseg * 8;

    auto issue_stage = [&](int s) {
        uint32_t sb = (uint32_t)((s % NPIPE) * STAGE_B);
        size_t gk = (size_t)s * 64;
#pragma unroll
        for (int i = 0; i < 4; i++) {
            uint32_t ro = (uint32_t)(((lrow + i * 32 + lplane) & 127) * 32)
                        + (uint32_t)(lplane * 4096 + lhalf * 16);
            cp16(smb + sb + ro,         gA + gk + (size_t)i * 32 * KX);
            cp16(smb + sb + 16384 + ro, gB + gk + (size_t)i * 32 * KX);
        }
        asm volatile("cp.async.commit_group;");
    };

    float acc[4][4][4];
#pragma unroll
    for (int a = 0; a < 4; a++)
#pragma unroll
        for (int b = 0; b < 4; b++)
#pragma unroll
            for (int r = 0; r < 4; r++) acc[a][b][r] = 0.0f;

    issue_stage(0);
    issue_stage(1);
    issue_stage(2);

    for (int s = 0; s < NSTAGE; s++) {
        asm volatile("cp.async.wait_group 2;");
        __syncthreads();
        uint32_t base = smb + (uint32_t)((s % NPIPE) * STAGE_B);
#pragma unroll
        for (int p = 0; p < 4; p++) {
            uint32_t abase = base + p * 4096;
            uint32_t bbase = abase + 16384;
            uint32_t brow0 = (uint32_t)(n0w + (lane & 7) + ((lane >> 4) << 3));
            uint32_t bhalf = (uint32_t)((lane >> 3) & 1);
            uint4 bf01 = ldsm_x4(bbase + (((brow0 + p) & 127) * 32) + bhalf * 16);
            uint4 bf23 = ldsm_x4(bbase + (((brow0 + 16 + p) & 127) * 32) + bhalf * 16);
            uint32_t arow = (uint32_t)(m0w + (lane & 15));
            uint32_t ahalf = (uint32_t)(lane >> 4);
            uint4 af[4];
#pragma unroll
            for (int im = 0; im < 4; im++)
                af[im] = ldsm_x4(abase + (((arow + im * 16 + p) & 127) * 32) + ahalf * 16);
#pragma unroll
            for (int im = 0; im < 4; im++) {
                mma16816(acc[im][0], af[im], bf01.x, bf01.y);
                mma16816(acc[im][1], af[im], bf01.z, bf01.w);
                mma16816(acc[im][2], af[im], bf23.x, bf23.y);
                mma16816(acc[im][3], af[im], bf23.z, bf23.w);
            }
        }
        __syncthreads();
        if (s + NPIPE < NSTAGE) issue_stage(s + NPIPE);
        else asm volatile("cp.async.commit_group;");
    }

    // ---------------- epilogue ----------------
    int gm = lane >> 2, gn = 2 * (lane & 3);
    if (EPI == 0) {
#pragma unroll
        for (int im = 0; im < 4; im++) {
#pragma unroll
            for (int jn = 0; jn < 4; jn++) {
                int col = v0 + n0w + jn * 8 + gn;
                float2 bb = *(const float2*)(bias0 + col);
                int row = i0 + m0w + im * 16 + gm;
                float2 o0 = make_float2(acc[im][jn][0] + bb.x, acc[im][jn][1] + bb.y);
                float2 o1 = make_float2(acc[im][jn][2] + bb.x, acc[im][jn][3] + bb.y);
                __stcs((float2*)(out + (size_t)row * VOCAB + col), o0);
                __stcs((float2*)(out + (size_t)(row + 8) * VOCAB + col), o1);
            }
        }
    } else {
#pragma unroll
        for (int im = 0; im < 4; im++) {
#pragma unroll
            for (int jn = 0; jn < 4; jn++) {
                int col = v0 + n0w + jn * 8 + gn;
                float b0 = bias0[col] + bias1[col];
                float b1 = bias0[col + 1] + bias1[col + 1];
                int r0 = i0 + m0w + im * 16 + gm;
                int r1 = r0 + 8;
                size_t base0 = (size_t)(r0 >> 5) * (G4 * BATCH) + (r0 & 31);
                size_t base1 = (size_t)(r1 >> 5) * (G4 * BATCH) + (r1 & 31);
                g_XPt[base0 + (size_t)col * 32]       = acc[im][jn][0] + b0;
                g_XPt[base0 + (size_t)(col + 1) * 32] = acc[im][jn][1] + b1;
                g_XPt[base1 + (size_t)col * 32]       = acc[im][jn][2] + b0;
                g_XPt[base1 + (size_t)(col + 1) * 32] = acc[im][jn][3] + b1;
            }
        }
    }
}

// ================= split kernels (fp32 -> bf16 hi/lo, folded-K layout) =================
// A-side layout: [hi | hi | lo].  B-side layout: [hi | lo | hi].
__device__ __forceinline__ void split_row(const float4 w, __nv_bfloat16* row, int k, bool aside) {
    __nv_bfloat16 h0 = __float2bfloat16_rn(w.x), h1 = __float2bfloat16_rn(w.y);
    __nv_bfloat16 h2 = __float2bfloat16_rn(w.z), h3 = __float2bfloat16_rn(w.w);
    __nv_bfloat16 l0 = __float2bfloat16_rn(w.x - __bfloat162float(h0));
    __nv_bfloat16 l1 = __float2bfloat16_rn(w.y - __bfloat162float(h1));
    __nv_bfloat16 l2 = __float2bfloat16_rn(w.z - __bfloat162float(h2));
    __nv_bfloat16 l3 = __float2bfloat16_rn(w.w - __bfloat162float(h3));
    ushort4 hv = make_ushort4(__bfloat16_as_ushort(h0), __bfloat16_as_ushort(h1),
                              __bfloat16_as_ushort(h2), __bfloat16_as_ushort(h3));
    ushort4 lv = make_ushort4(__bfloat16_as_ushort(l0), __bfloat16_as_ushort(l1),
                              __bfloat16_as_ushort(l2), __bfloat16_as_ushort(l3));
    *(ushort4*)(row + k) = hv;
    if (aside) {
        *(ushort4*)(row + 512 + k)  = hv;
        *(ushort4*)(row + 1024 + k) = lv;
    } else {
        *(ushort4*)(row + 512 + k)  = lv;
        *(ushort4*)(row + 1024 + k) = hv;
    }
}

__global__ void split_W(const float* __restrict__ W_fc) {
    int idx = blockIdx.x * 256 + threadIdx.x;        // 32000*128
    int v = idx >> 7, q = idx & 127;
    float4 w = *(const float4*)(W_fc + (size_t)v * HDIM + q * 4);
    split_row(w, g_WX + (size_t)v * KX, q * 4, false);
}
__global__ void split_WI(const float* __restrict__ W_ih) {
    int idx = blockIdx.x * 256 + threadIdx.x;        // 2048*128
    int v = idx >> 7, q = idx & 127;
    float4 w = *(const float4*)(W_ih + (size_t)v * HDIM + q * 4);
    split_row(w, g_WIX + (size_t)v * KX, q * 4, false);
}
__global__ void split_E(const int* __restrict__ tokens, const float* __restrict__ emb) {
    int idx = blockIdx.x * 256 + threadIdx.x;        // 2048*128
    int i = idx >> 7, q = idx & 127;
    int tok = tokens[i];
    float4 w = *(const float4*)(emb + (size_t)tok * HDIM + q * 4);
    split_row(w, g_EX + (size_t)i * KX, q * 4, true);
}
__global__ void split_H(void) {
    int idx = blockIdx.x * 256 + threadIdx.x;        // 2048*128
    int i = idx >> 7, q = idx & 127;
    float4 w = *(const float4*)(g_H + (size_t)i * HDIM + q * 4);
    split_row(w, g_HX + (size_t)i * KX, q * 4, true);
}

// ================= one-time W_hh transpose =================
__global__ void prep_W4(const float* __restrict__ W_hh) {
    int idx = blockIdx.x * 256 + threadIdx.x;
    int j = idx >> 9, k = idx & 511;
    g_W4[(size_t)j * 512 + k] = make_float4(
        W_hh[(size_t)(0 * 512 + j) * 512 + k],
        W_hh[(size_t)(1 * 512 + j) * 512 + k],
        W_hh[(size_t)(2 * 512 + j) * 512 + k],
        W_hh[(size_t)(3 * 512 + j) * 512 + k]);
}

// ================= init =================
__global__ void init_kernel(const float* __restrict__ h0, const float* __restrict__ c0) {
    int idx = blockIdx.x * blockDim.x + threadIdx.x;
    if (idx < BATCH * HDIM) {
        int j = idx >> 5, b = idx & 31;
        ((float*)g_hT4[0])[(j >> 2) * 128 + b * 4 + (j & 3)] = h0[b * HDIM + j];
        g_cT[j * 32 + b] = c0[b * HDIM + j];
    }
}

// ================= recurrent step: K-split x8, CTA = one j (R6-proven, 11.2 us/step) =================
__global__ void __launch_bounds__(256, 4)
recurrent_kernel(const int* __restrict__ tokens, int t) {
    __shared__ float4 sred[8][32];
    int tid = threadIdx.x;
    int w = tid >> 5, b = tid & 31;
    int j = blockIdx.x;

    const float4*  hT = g_hT4[t & 1];
    const double2* wp = (const double2*)(g_W4 + (size_t)j * 512) + (size_t)w * 64;
    const float4*  hp = hT + w * 16 * 32;

    ull aif0 = pack2(0.0f, 0.0f), aif1 = pack2(0.0f, 0.0f);
    ull ago0 = pack2(0.0f, 0.0f), ago1 = pack2(0.0f, 0.0f);

#pragma unroll
    for (int kk = 0; kk < 16; kk++) {
        float4  h4 = hp[kk * 32 + b];
        double2 w0 = wp[kk * 4 + 0];
        double2 w1 = wp[kk * 4 + 1];
        double2 w2 = wp[kk * 4 + 2];
        double2 w3 = wp[kk * 4 + 3];
        ull hx = pack2(h4.x, h4.x), hy = pack2(h4.y, h4.y);
        ull hz = pack2(h4.z, h4.z), hw = pack2(h4.w, h4.w);
        ffma2(aif0, hx, d2u(w0.x));
        ffma2(ago0, hx, d2u(w0.y));
        ffma2(aif1, hy, d2u(w1.x));
        ffma2(ago1, hy, d2u(w1.y));
        ffma2(aif0, hz, d2u(w2.x));
        ffma2(ago0, hz, d2u(w2.y));
        ffma2(aif1, hw, d2u(w3.x));
        ffma2(ago1, hw, d2u(w3.y));
    }

    float ia, fa, ib, fb, ga, oa, gb, ob;
    unpack2(aif0, ia, fa); unpack2(aif1, ib, fb);
    unpack2(ago0, ga, oa); unpack2(ago1, gb, ob);
    sred[w][b] = make_float4(ia + ib, fa + fb, ga + gb, oa + ob);
    __syncthreads();

    if (w == 0) {
        float4 acc4 = sred[0][b];
#pragma unroll
        for (int q = 1; q < 8; q++) {
            float4 s = sred[q][b];
            acc4.x += s.x; acc4.y += s.y; acc4.z += s.z; acc4.w += s.w;
        }
        size_t xb = (size_t)t * (G4 * BATCH) + (size_t)b;
        float ig = acc4.x + g_XPt[xb + (size_t)(0 * 512 + j) * 32];
        float fg = acc4.y + g_XPt[xb + (size_t)(1 * 512 + j) * 32];
        float gg = acc4.z + g_XPt[xb + (size_t)(2 * 512 + j) * 32];
        float og = acc4.w + g_XPt[xb + (size_t)(3 * 512 + j) * 32];

        float iv = 1.0f / (1.0f + expf(-ig));
        float fv = 1.0f / (1.0f + expf(-fg));
        float gv = tanhf(gg);
        float ov = 1.0f / (1.0f + expf(-og));

        float cold = g_cT[j * 32 + b];
        float ctmp = fv * cold + iv * gv;
        float htmp = ov * tanhf(ctmp);
        bool  msk  = tokens[t * BATCH + b] != 0;   // PAD = 0

        g_H[((size_t)t * BATCH + b) * HDIM + j] = htmp;
        float hold = ((const float*)hT)[(j >> 2) * 128 + b * 4 + (j & 3)];
        ((float*)g_hT4[(t + 1) & 1])[(j >> 2) * 128 + b * 4 + (j & 3)] = msk ? htmp : hold;
        g_cT[j * 32 + b] = msk ? ctmp : cold;
    }
}

// ================= launch =================
extern "C" void kernel_launch(void* const* d_in, const int* in_sizes, int n_in,
                              void* d_out, int out_size) {
    const int*   tokens = (const int*)d_in[0];
    const float* emb    = (const float*)d_in[1];
    const float* W_ih   = (const float*)d_in[2];
    const float* W_hh   = (const float*)d_in[3];
    const float* b_ih   = (const float*)d_in[4];
    const float* b_hh   = (const float*)d_in[5];
    const float* W_fc   = (const float*)d_in[6];
    const float* b_fc   = (const float*)d_in[7];
    const float* h0     = (const float*)d_in[8];
    const float* c0     = (const float*)d_in[9];
    float* out = (float*)d_out;

    cudaFuncSetAttribute(mma_gemm<0>, cudaFuncAttributeMaxDynamicSharedMemorySize, GEMM_SMEM);
    cudaFuncSetAttribute(mma_gemm<1>, cudaFuncAttributeMaxDynamicSharedMemorySize, GEMM_SMEM);

    init_kernel<<<64, 256>>>(h0, c0);
    prep_W4<<<1024, 256>>>(W_hh);
    split_W<<<16000, 256>>>(W_fc);
    split_WI<<<1024, 256>>>(W_ih);
    split_E<<<1024, 256>>>(tokens, emb);

    // XPt = emb[tok] @ W_ih^T + (b_ih + b_hh):  M=2048, N=2048, K'=1536 (HMMA bf16x3)
    mma_gemm<1><<<dim3(16, 16), 256, GEMM_SMEM>>>(b_ih, b_hh, nullptr);

    // 64 LSTM steps, one launch each (R6-proven 512-CTA kernel)
    for (int t = 0; t < T_STEPS; t++)
        recurrent_kernel<<<512, 256>>>(tokens, t);

    split_H<<<1024, 256>>>();

    // out = HX @ WX^T + b_fc:  M=2048, N=32000, K'=1536 (HMMA bf16x3, 3-stage pipeline)
    mma_gemm<0><<<dim3(16, 250), 256, GEMM_SMEM>>>(b_fc, nullptr, out);
}